// round 6
// baseline (speedup 1.0000x reference)
#include <cuda_runtime.h>
#include <cuda_bf16.h>
#include <cstdint>

// B=32, P=512, S=1024, H=1024, R=256, K3=3072
// out[M=16384,256] = feats[M,3072] @ W^T + bias (feats gathered on the fly)
// mma.sync bf16 split: D += Ahi*Bhi + Ahi*Blo + Alo*Bhi (fp32 accum)
// R6: pre-split W (prologue kernel) + cp.async B staging + double-buffered
// SMEM with stage(c+1)/compute(c) overlap.

#define THREADS 512

// ---- pre-split W storage (device globals: legal scratch) ----
__device__ __nv_bfloat16 g_Whi[256 * 3072];
__device__ __nv_bfloat16 g_Wlo[256 * 3072];

static __device__ __forceinline__ uint32_t smem_u32(const void* p) {
    uint32_t a;
    asm("{ .reg .u64 t; cvta.to.shared.u64 t, %1; cvt.u32.u64 %0, t; }"
        : "=r"(a) : "l"(p));
    return a;
}
static __device__ __forceinline__ void ldsm4(uint32_t* r, uint32_t addr) {
    asm volatile("ldmatrix.sync.aligned.m8n8.x4.shared.b16 {%0,%1,%2,%3}, [%4];"
                 : "=r"(r[0]), "=r"(r[1]), "=r"(r[2]), "=r"(r[3]) : "r"(addr));
}
static __device__ __forceinline__ void mma_bf16(float* d, const uint32_t* a,
                                                const uint32_t* b) {
    asm volatile("mma.sync.aligned.m16n8k16.row.col.f32.bf16.bf16.f32 "
                 "{%0,%1,%2,%3}, {%4,%5,%6,%7}, {%8,%9}, {%0,%1,%2,%3};"
                 : "+f"(d[0]), "+f"(d[1]), "+f"(d[2]), "+f"(d[3])
                 : "r"(a[0]), "r"(a[1]), "r"(a[2]), "r"(a[3]),
                   "r"(b[0]), "r"(b[1]));
}
static __device__ __forceinline__ void cpasync16(uint32_t dst, const void* src) {
    asm volatile("cp.async.ca.shared.global [%0], [%1], 16;"
                 :: "r"(dst), "l"(src) : "memory");
}
static __device__ __forceinline__ void split2(float a, float b,
                                              uint32_t& hi, uint32_t& lo) {
    __nv_bfloat16 ah = __float2bfloat16(a), bh = __float2bfloat16(b);
    __nv_bfloat16 al = __float2bfloat16(a - __bfloat162float(ah));
    __nv_bfloat16 bl = __float2bfloat16(b - __bfloat162float(bh));
    hi = (uint32_t)__bfloat16_as_ushort(ah) | ((uint32_t)__bfloat16_as_ushort(bh) << 16);
    lo = (uint32_t)__bfloat16_as_ushort(al) | ((uint32_t)__bfloat16_as_ushort(bl) << 16);
}

// SMEM geometry: rows padded to 72 bf16 (144 B -> conflict-free ldmatrix)
#define LDA 72
#define OFF_AHI 0
#define OFF_ALO (128 * LDA * 2)             // 18432
#define OFF_BHI (2 * 128 * LDA * 2)         // 36864
#define OFF_BLO (OFF_BHI + 256 * LDA * 2)   // 73728
#define BUF_STRIDE (OFF_BHI + 2 * 256 * LDA * 2)   // 110592
#define SMEM_BYTES (2 * BUF_STRIDE)                // 221184

// ---- prologue: split W f32 -> bf16 hi/lo ----
__global__ void w_split_kernel(const float* __restrict__ Wg) {
    const int i = (blockIdx.x * blockDim.x + threadIdx.x);   // float4 index
    if (i >= 256 * 3072 / 4) return;
    float4 v = reinterpret_cast<const float4*>(Wg)[i];
    uint32_t h0, l0, h1, l1;
    split2(v.x, v.y, h0, l0);
    split2(v.z, v.w, h1, l1);
    reinterpret_cast<uint2*>(g_Whi)[i] = make_uint2(h0, h1);
    reinterpret_cast<uint2*>(g_Wlo)[i] = make_uint2(l0, l1);
}

__global__ void __launch_bounds__(THREADS, 1)
gr_mma_gemm_kernel(const int*   __restrict__ pairs32,
                   const float* __restrict__ hidden,
                   const float* __restrict__ bias,
                   float*       __restrict__ out)
{
    constexpr int H   = 1024;
    constexpr int MT  = 128;
    constexpr int KC  = 64;
    constexpr int NCH = 3072 / KC;   // 48

    extern __shared__ char dsm[];
    const uint32_t smb = smem_u32(dsm);

    __shared__ int4  sIdx[MT];
    __shared__ float sBias[256];
    __shared__ int   sIs64;

    const int t    = threadIdx.x;
    const int lane = t & 31;
    const int w    = t >> 5;
    const int wm   = w & 3;
    const int wn   = w >> 2;

    const int row0 = blockIdx.x * MT;
    const int b    = row0 >> 9;
    const int p0   = row0 & 511;

    if (t == 0) {
        int a = 0;
#pragma unroll
        for (int i = 1; i < 128; i += 2) a |= pairs32[i];
        sIs64 = (a == 0);
    }
    if (t < 256) sBias[t] = bias[t];
    __syncthreads();

    if (t < MT) {
        const size_t pidx = (size_t)b * 512 + p0 + t;
        if (sIs64) {
            const long long* p64 = reinterpret_cast<const long long*>(pairs32) + pidx * 4;
            sIdx[t] = make_int4((int)p64[0], (int)p64[1], (int)p64[2], (int)p64[3]);
        } else {
            sIdx[t] = reinterpret_cast<const int4*>(pairs32)[pidx];
        }
    }
    __syncthreads();

    const float* hb = hidden + (size_t)b * (size_t)(H * 1024);

    // A staging map: 4 thr/row, 16 k each
    const int arow  = t >> 2;
    const int akoff = (t & 3) << 4;
    const int4 id   = sIdx[arow];
    // B staging map: 2 thr/row, 64 B (32 bf16) each via 4x cp.async16
    const int brow  = t >> 1;
    const int bkoff = (t & 1) << 5;
    const __nv_bfloat16* bhis = g_Whi + (size_t)brow * 3072 + bkoff;
    const __nv_bfloat16* blos = g_Wlo + (size_t)brow * 3072 + bkoff;
    const uint32_t bdst = (brow * LDA + bkoff) * 2;

    float acc[2][8][4];
#pragma unroll
    for (int i = 0; i < 2; ++i)
#pragma unroll
        for (int j = 0; j < 8; ++j)
#pragma unroll
            for (int q = 0; q < 4; ++q) acc[i][j][q] = 0.f;

    // ldmatrix lane address components
    const int lr = lane & 15;
    const int lh = (lane >> 4) << 3;
    const uint32_t aOff = ((wm * 32 + lr) * LDA + lh) * 2;  // + OFF_AHI
    const uint32_t bOff = ((wn * 64 + lr) * LDA + lh) * 2;  // + OFF_BHI

    // ---- staging lambdas ----
    auto stage_B = [&](int c) {
        const uint32_t dst = smb + (c & 1) * BUF_STRIDE + bdst;
#pragma unroll
        for (int i = 0; i < 4; ++i) {
            cpasync16(dst + OFF_BHI + i * 16, bhis + c * KC + i * 8);
            cpasync16(dst + OFF_BLO + i * 16, blos + c * KC + i * 8);
        }
    };
    auto stage_A = [&](int c) {
        const int s  = c >> 4;
        const int hk = ((c & 15) << 6) + akoff;
        const uint32_t dst = smb + (c & 1) * BUF_STRIDE + (arow * LDA + akoff) * 2;
        const float4* q0 = reinterpret_cast<const float4*>(hb + (size_t)id.x * H + hk);
        const float4* q1 = reinterpret_cast<const float4*>(hb + (size_t)id.y * H + hk);
        const float4* q2 = reinterpret_cast<const float4*>(hb + (size_t)id.z * H + hk);
        const float4* q3 = reinterpret_cast<const float4*>(hb + (size_t)id.w * H + hk);
#pragma unroll
        for (int i = 0; i < 4; ++i) {
            float4 v;
            if (s == 0) {
                float4 a = q0[i], d = q1[i];
                v.x = 0.5f*(a.x+d.x); v.y = 0.5f*(a.y+d.y);
                v.z = 0.5f*(a.z+d.z); v.w = 0.5f*(a.w+d.w);
            } else if (s == 1) {
                float4 a = q2[i], d = q3[i];
                v.x = 0.5f*(a.x+d.x); v.y = 0.5f*(a.y+d.y);
                v.z = 0.5f*(a.z+d.z); v.w = 0.5f*(a.w+d.w);
            } else {
                float4 a = q0[i], e = q1[i], f = q2[i], g = q3[i];
                v.x = 0.25f*(a.x+e.x)*(f.x+g.x);
                v.y = 0.25f*(a.y+e.y)*(f.y+g.y);
                v.z = 0.25f*(a.z+e.z)*(f.z+g.z);
                v.w = 0.25f*(a.w+e.w)*(f.w+g.w);
            }
            uint32_t h0, l0, h1, l1;
            split2(v.x, v.y, h0, l0);
            split2(v.z, v.w, h1, l1);
            asm volatile("st.shared.v2.b32 [%0], {%1, %2};"
                         :: "r"(dst + OFF_AHI + i * 8), "r"(h0), "r"(h1));
            asm volatile("st.shared.v2.b32 [%0], {%1, %2};"
                         :: "r"(dst + OFF_ALO + i * 8), "r"(l0), "r"(l1));
        }
    };

    // ---- prologue: stage chunk 0 ----
    stage_B(0);
    stage_A(0);
    asm volatile("cp.async.commit_group;");
    asm volatile("cp.async.wait_group 0;" ::: "memory");
    __syncthreads();

    for (int c = 0; c < NCH; ++c) {
        // stage next chunk into the other buffer (overlapped with compute)
        if (c + 1 < NCH) {
            stage_B(c + 1);
            asm volatile("cp.async.commit_group;");
            stage_A(c + 1);
        }

        // ---- compute chunk c ----
        const uint32_t base  = smb + (c & 1) * BUF_STRIDE;
        const uint32_t aBase = base + OFF_AHI + aOff;
        const uint32_t bBase = base + OFF_BHI + bOff;
#pragma unroll
        for (int kk = 0; kk < KC; kk += 16) {
            const uint32_t kb = kk * 2;
            uint32_t a_hi[2][4], b_f[8][2];
#pragma unroll
            for (int mt = 0; mt < 2; ++mt)
                ldsm4(a_hi[mt], aBase + (mt * 16 * LDA) * 2 + kb);
#pragma unroll
            for (int p = 0; p < 4; ++p) {
                uint32_t r[4];
                ldsm4(r, bBase + (p * 16 * LDA) * 2 + kb);
                b_f[2*p][0]   = r[0]; b_f[2*p][1]   = r[2];
                b_f[2*p+1][0] = r[1]; b_f[2*p+1][1] = r[3];
            }
#pragma unroll
            for (int mt = 0; mt < 2; ++mt)
#pragma unroll
                for (int n8 = 0; n8 < 8; ++n8)
                    mma_bf16(acc[mt][n8], a_hi[mt], b_f[n8]);
            {
                uint32_t a_lo[2][4];
#pragma unroll
                for (int mt = 0; mt < 2; ++mt)
                    ldsm4(a_lo[mt], aBase + (OFF_ALO - OFF_AHI) + (mt * 16 * LDA) * 2 + kb);
#pragma unroll
                for (int mt = 0; mt < 2; ++mt)
#pragma unroll
                    for (int n8 = 0; n8 < 8; ++n8)
                        mma_bf16(acc[mt][n8], a_lo[mt], b_f[n8]);
            }
#pragma unroll
            for (int p = 0; p < 4; ++p) {
                uint32_t r[4];
                ldsm4(r, bBase + (OFF_BLO - OFF_BHI) + (p * 16 * LDA) * 2 + kb);
                b_f[2*p][0]   = r[0]; b_f[2*p][1]   = r[2];
                b_f[2*p+1][0] = r[1]; b_f[2*p+1][1] = r[3];
            }
#pragma unroll
            for (int mt = 0; mt < 2; ++mt)
#pragma unroll
                for (int n8 = 0; n8 < 8; ++n8)
                    mma_bf16(acc[mt][n8], a_hi[mt], b_f[n8]);
        }

        asm volatile("cp.async.wait_group 0;" ::: "memory");
        __syncthreads();
    }

    // ---- epilogue ----
    const int g  = lane >> 2;
    const int tq = lane & 3;
#pragma unroll
    for (int mt = 0; mt < 2; ++mt) {
        const int r0g = row0 + wm * 32 + mt * 16 + g;
#pragma unroll
        for (int n8 = 0; n8 < 8; ++n8) {
            const int col = wn * 64 + n8 * 8 + tq * 2;
            const float bx = sBias[col], by = sBias[col + 1];
            float* o0 = out + (size_t)r0g * 256 + col;
            float* o1 = o0 + 8 * 256;
            *reinterpret_cast<float2*>(o0) =
                make_float2(acc[mt][n8][0] + bx, acc[mt][n8][1] + by);
            *reinterpret_cast<float2*>(o1) =
                make_float2(acc[mt][n8][2] + bx, acc[mt][n8][3] + by);
        }
    }
}

extern "C" void kernel_launch(void* const* d_in, const int* in_sizes, int n_in,
                              void* d_out, int out_size) {
    (void)in_sizes; (void)n_in; (void)out_size;
    const int*   pairs  = (const int*)  d_in[0];
    const float* hidden = (const float*)d_in[1];
    const float* W      = (const float*)d_in[2];
    const float* bias   = (const float*)d_in[3];
    float*       out    = (float*)d_out;

    static bool attr_set = false;
    if (!attr_set) {
        cudaFuncSetAttribute(gr_mma_gemm_kernel,
                             cudaFuncAttributeMaxDynamicSharedMemorySize, SMEM_BYTES);
        attr_set = true;
    }
    w_split_kernel<<<(256 * 3072 / 4 + 511) / 512, 512>>>(W);
    gr_mma_gemm_kernel<<<16384 / 128, THREADS, SMEM_BYTES>>>(pairs, hidden, bias, out);
}

// round 7
// speedup vs baseline: 1.8080x; 1.8080x over previous
#include <cuda_runtime.h>
#include <cuda_fp16.h>
#include <cstdint>

// B=32, P=512, S=1024, H=1024, R=256, K3=3072
// out[M=16384,256] = feats[M,3072] @ W^T + bias (feats gathered on the fly)
// R7: single-pass fp16 HMMA (err ~4e-4 global-norm, threshold 1e-3).
// CTA 128x256, 256 thr (8 warps, 2x4), warp tile 64x64, KC=64,
// double-buffered; B via cp.async from pre-converted g_Wh; A staged
// STORE-LATE (gather->build->cvt->STS after compute) so LDG latency is
// overlapped by the MMA block instead of stalling ahead of it (R6 bug).

#define THREADS 256

__device__ __half g_Wh[256 * 3072];   // W pre-converted to fp16 (prologue)

static __device__ __forceinline__ uint32_t smem_u32(const void* p) {
    uint32_t a;
    asm("{ .reg .u64 t; cvta.to.shared.u64 t, %1; cvt.u32.u64 %0, t; }"
        : "=r"(a) : "l"(p));
    return a;
}
static __device__ __forceinline__ void ldsm4(uint32_t* r, uint32_t addr) {
    asm volatile("ldmatrix.sync.aligned.m8n8.x4.shared.b16 {%0,%1,%2,%3}, [%4];"
                 : "=r"(r[0]), "=r"(r[1]), "=r"(r[2]), "=r"(r[3]) : "r"(addr));
}
static __device__ __forceinline__ void mma_f16(float* d, const uint32_t* a,
                                               const uint32_t* b) {
    asm volatile("mma.sync.aligned.m16n8k16.row.col.f32.f16.f16.f32 "
                 "{%0,%1,%2,%3}, {%4,%5,%6,%7}, {%8,%9}, {%0,%1,%2,%3};"
                 : "+f"(d[0]), "+f"(d[1]), "+f"(d[2]), "+f"(d[3])
                 : "r"(a[0]), "r"(a[1]), "r"(a[2]), "r"(a[3]),
                   "r"(b[0]), "r"(b[1]));
}
static __device__ __forceinline__ void cpasync16(uint32_t dst, const void* src) {
    asm volatile("cp.async.ca.shared.global [%0], [%1], 16;"
                 :: "r"(dst), "l"(src) : "memory");
}
static __device__ __forceinline__ uint32_t h2bits(__half2 h) {
    return *reinterpret_cast<uint32_t*>(&h);
}

// SMEM: rows padded to 72 fp16 (144 B pitch -> conflict-free ldmatrix)
#define LDA 72
#define PITCH (LDA * 2)                       // 144 B
#define OFF_A 0
#define OFF_B (128 * PITCH)                   // 18432
#define BUF_STRIDE (OFF_B + 256 * PITCH)      // 55296
#define SMEM_BYTES (2 * BUF_STRIDE)           // 110592

// ---- prologue: W f32 -> fp16 (round-to-nearest) ----
__global__ void w_cvt_kernel(const float* __restrict__ Wg) {
    const int i = blockIdx.x * blockDim.x + threadIdx.x;   // float4 index
    if (i >= 256 * 3072 / 4) return;
    float4 v = reinterpret_cast<const float4*>(Wg)[i];
    __half2 h0 = __float22half2_rn(make_float2(v.x, v.y));
    __half2 h1 = __float22half2_rn(make_float2(v.z, v.w));
    reinterpret_cast<uint2*>(g_Wh)[i] = make_uint2(h2bits(h0), h2bits(h1));
}

__global__ void __launch_bounds__(THREADS, 1)
gr_f16_gemm_kernel(const int*   __restrict__ pairs32,
                   const float* __restrict__ hidden,
                   const float* __restrict__ bias,
                   float*       __restrict__ out)
{
    constexpr int H   = 1024;
    constexpr int MT  = 128;
    constexpr int KC  = 64;
    constexpr int NCH = 3072 / KC;   // 48

    extern __shared__ char dsm[];
    const uint32_t smb = smem_u32(dsm);

    __shared__ int4  sIdx[MT];
    __shared__ float sBias[256];
    __shared__ int   sIs64;

    const int t    = threadIdx.x;
    const int lane = t & 31;
    const int w    = t >> 5;
    const int wm   = w >> 2;       // 0..1: 64-row m group
    const int wn   = w & 3;        // 0..3: 64-col n group

    const int row0 = blockIdx.x * MT;
    const int b    = row0 >> 9;
    const int p0   = row0 & 511;

    // pairs dtype sniff: int64 -> all odd 32-bit words zero (indices < 1024)
    if (t == 0) {
        int a = 0;
#pragma unroll
        for (int i = 1; i < 128; i += 2) a |= pairs32[i];
        sIs64 = (a == 0);
    }
    sBias[t] = bias[t];
    __syncthreads();

    if (t < MT) {
        const size_t pidx = (size_t)b * 512 + p0 + t;
        if (sIs64) {
            const long long* p64 = reinterpret_cast<const long long*>(pairs32) + pidx * 4;
            sIdx[t] = make_int4((int)p64[0], (int)p64[1], (int)p64[2], (int)p64[3]);
        } else {
            sIdx[t] = reinterpret_cast<const int4*>(pairs32)[pidx];
        }
    }
    __syncthreads();

    const float* hb = hidden + (size_t)b * (size_t)(H * 1024);

    // A staging: 2 thr/row, 32 k each. B staging: 1 thr/row, 64 fp16 = 128 B.
    const int arow  = t >> 1;
    const int akoff = (t & 1) << 5;
    const int4 id   = sIdx[arow];
    const __half* wsrc = g_Wh + (size_t)t * 3072;

    float acc[4][8][4];
#pragma unroll
    for (int i = 0; i < 4; ++i)
#pragma unroll
        for (int j = 0; j < 8; ++j)
#pragma unroll
            for (int q = 0; q < 4; ++q) acc[i][j][q] = 0.f;

    // ldmatrix lane address components
    const int lr = lane & 15;
    const int lh = (lane >> 4) << 3;
    const uint32_t aOff = OFF_A + (wm * 64 + lr) * PITCH + lh * 2;
    const uint32_t bOff = OFF_B + (wn * 64 + lr) * PITCH + lh * 2;

    auto stage_B = [&](int c) {   // cp.async, latency-free issue
        const uint32_t dst = smb + (c & 1) * BUF_STRIDE + OFF_B + t * PITCH;
        const __half* src = wsrc + c * KC;
#pragma unroll
        for (int i = 0; i < 8; ++i)
            cpasync16(dst + i * 16, src + i * 8);
    };
    auto stage_A = [&](int c) {   // gather + feature + cvt + STS (store-late)
        const int s  = c >> 4;
        const int hk = ((c & 15) << 6) + akoff;
        char* dst = dsm + (c & 1) * BUF_STRIDE + OFF_A + arow * PITCH + akoff * 2;
        const float4* q0 = reinterpret_cast<const float4*>(hb + (size_t)id.x * H + hk);
        const float4* q1 = reinterpret_cast<const float4*>(hb + (size_t)id.y * H + hk);
        const float4* q2 = reinterpret_cast<const float4*>(hb + (size_t)id.z * H + hk);
        const float4* q3 = reinterpret_cast<const float4*>(hb + (size_t)id.w * H + hk);
#pragma unroll
        for (int i = 0; i < 8; ++i) {
            float4 v;
            if (s == 0) {
                float4 a = q0[i], d = q1[i];
                v.x = 0.5f*(a.x+d.x); v.y = 0.5f*(a.y+d.y);
                v.z = 0.5f*(a.z+d.z); v.w = 0.5f*(a.w+d.w);
            } else if (s == 1) {
                float4 a = q2[i], d = q3[i];
                v.x = 0.5f*(a.x+d.x); v.y = 0.5f*(a.y+d.y);
                v.z = 0.5f*(a.z+d.z); v.w = 0.5f*(a.w+d.w);
            } else {
                float4 a = q0[i], e = q1[i], f = q2[i], g = q3[i];
                v.x = 0.25f*(a.x+e.x)*(f.x+g.x);
                v.y = 0.25f*(a.y+e.y)*(f.y+g.y);
                v.z = 0.25f*(a.z+e.z)*(f.z+g.z);
                v.w = 0.25f*(a.w+e.w)*(f.w+g.w);
            }
            __half2 h0 = __float22half2_rn(make_float2(v.x, v.y));
            __half2 h1 = __float22half2_rn(make_float2(v.z, v.w));
            *reinterpret_cast<uint2*>(dst + i * 8) = make_uint2(h2bits(h0), h2bits(h1));
        }
    };

    // ---- prologue: stage chunk 0 ----
    stage_B(0);
    asm volatile("cp.async.commit_group;");
    stage_A(0);
    asm volatile("cp.async.wait_group 0;" ::: "memory");
    __syncthreads();

    for (int c = 0; c < NCH; ++c) {
        if (c + 1 < NCH) {
            stage_B(c + 1);                       // async, no stall
            asm volatile("cp.async.commit_group;");
        }

        // ---- compute chunk c: 4 k16-steps, 8 ldsm + 32 HMMA each ----
        const uint32_t base  = smb + (c & 1) * BUF_STRIDE;
        const uint32_t aBase = base + aOff;
        const uint32_t bBase = base + bOff;
#pragma unroll
        for (int kk = 0; kk < 4; ++kk) {
            const uint32_t kb = kk * 32;
            uint32_t af[4][4], bf[8][2];
#pragma unroll
            for (int mt = 0; mt < 4; ++mt)
                ldsm4(af[mt], aBase + mt * 16 * PITCH + kb);
#pragma unroll
            for (int p = 0; p < 4; ++p) {
                uint32_t r[4];
                ldsm4(r, bBase + p * 16 * PITCH + kb);
                bf[2*p][0]   = r[0]; bf[2*p][1]   = r[2];
                bf[2*p+1][0] = r[1]; bf[2*p+1][1] = r[3];
            }
#pragma unroll
            for (int mt = 0; mt < 4; ++mt)
#pragma unroll
                for (int n8 = 0; n8 < 8; ++n8)
                    mma_f16(acc[mt][n8], af[mt], bf[n8]);
        }

        if (c + 1 < NCH) stage_A(c + 1);          // store-late: after MMAs

        asm volatile("cp.async.wait_group 0;" ::: "memory");
        __syncthreads();
    }

    // ---- epilogue: add bias, write fp32 ----
    const int g  = lane >> 2;
    const int tq = lane & 3;
#pragma unroll
    for (int mt = 0; mt < 4; ++mt) {
        const int r0g = row0 + wm * 64 + mt * 16 + g;
#pragma unroll
        for (int n8 = 0; n8 < 8; ++n8) {
            const int col = wn * 64 + n8 * 8 + tq * 2;
            const float bx = sBias[col], by = sBias[col + 1];
            float* o0 = out + (size_t)r0g * 256 + col;
            float* o1 = o0 + 8 * 256;
            *reinterpret_cast<float2*>(o0) =
                make_float2(acc[mt][n8][0] + bx, acc[mt][n8][1] + by);
            *reinterpret_cast<float2*>(o1) =
                make_float2(acc[mt][n8][2] + bx, acc[mt][n8][3] + by);
        }
    }
}

extern "C" void kernel_launch(void* const* d_in, const int* in_sizes, int n_in,
                              void* d_out, int out_size) {
    (void)in_sizes; (void)n_in; (void)out_size;
    const int*   pairs  = (const int*)  d_in[0];
    const float* hidden = (const float*)d_in[1];
    const float* W      = (const float*)d_in[2];
    const float* bias   = (const float*)d_in[3];
    float*       out    = (float*)d_out;

    static bool attr_set = false;
    if (!attr_set) {
        cudaFuncSetAttribute(gr_f16_gemm_kernel,
                             cudaFuncAttributeMaxDynamicSharedMemorySize, SMEM_BYTES);
        attr_set = true;
    }
    w_cvt_kernel<<<(256 * 3072 / 4 + 255) / 256, 256>>>(W);
    gr_f16_gemm_kernel<<<16384 / 128, THREADS, SMEM_BYTES>>>(pairs, hidden, bias, out);
}

// round 8
// speedup vs baseline: 3.0110x; 1.6654x over previous
#include <cuda_runtime.h>
#include <cuda_fp16.h>
#include <cstdint>

// B=32, P=512, S=1024, H=1024, R=256, K3=3072
// out[M=16384,256] = feats[M,3072] @ W^T + bias
// R8: DECOUPLED. feats_kernel materializes fp16 feats (gather+build+cvt);
// GEMM stages BOTH operands via cp.async (no staging registers -> no spills,
// the R7 killer: regs=255 with LDL/STL spill traffic through L1).

#define THREADS 256

__device__ __half g_Wh[256 * 3072];            // W as fp16
__device__ __half g_feats[16384 * 3072];       // feats as fp16 (96 MB scratch)

static __device__ __forceinline__ uint32_t smem_u32(const void* p) {
    uint32_t a;
    asm("{ .reg .u64 t; cvta.to.shared.u64 t, %1; cvt.u32.u64 %0, t; }"
        : "=r"(a) : "l"(p));
    return a;
}
static __device__ __forceinline__ void ldsm4(uint32_t* r, uint32_t addr) {
    asm volatile("ldmatrix.sync.aligned.m8n8.x4.shared.b16 {%0,%1,%2,%3}, [%4];"
                 : "=r"(r[0]), "=r"(r[1]), "=r"(r[2]), "=r"(r[3]) : "r"(addr));
}
static __device__ __forceinline__ void mma_f16(float* d, const uint32_t* a,
                                               const uint32_t* b) {
    asm volatile("mma.sync.aligned.m16n8k16.row.col.f32.f16.f16.f32 "
                 "{%0,%1,%2,%3}, {%4,%5,%6,%7}, {%8,%9}, {%0,%1,%2,%3};"
                 : "+f"(d[0]), "+f"(d[1]), "+f"(d[2]), "+f"(d[3])
                 : "r"(a[0]), "r"(a[1]), "r"(a[2]), "r"(a[3]),
                   "r"(b[0]), "r"(b[1]));
}
static __device__ __forceinline__ void cpasync16(uint32_t dst, const void* src) {
    asm volatile("cp.async.ca.shared.global [%0], [%1], 16;"
                 :: "r"(dst), "l"(src) : "memory");
}
static __device__ __forceinline__ uint32_t h2bits(__half2 h) {
    return *reinterpret_cast<uint32_t*>(&h);
}
static __device__ __forceinline__ uint2 pack4(float x, float y, float z, float w) {
    return make_uint2(h2bits(__float22half2_rn(make_float2(x, y))),
                      h2bits(__float22half2_rn(make_float2(z, w))));
}

// SMEM: rows padded to 72 fp16 (144 B pitch, 16B-aligned, conflict-free ldsm)
#define LDA 72
#define PITCH (LDA * 2)
#define OFF_A 0
#define OFF_B (128 * PITCH)                   // 18432
#define BUF_STRIDE (OFF_B + 256 * PITCH)      // 55296
#define SMEM_BYTES (2 * BUF_STRIDE)           // 110592

// ---- prologue 1: W f32 -> fp16 ----
__global__ void w_cvt_kernel(const float* __restrict__ Wg) {
    const int i = blockIdx.x * blockDim.x + threadIdx.x;
    if (i >= 256 * 3072 / 4) return;
    float4 v = reinterpret_cast<const float4*>(Wg)[i];
    reinterpret_cast<uint2*>(g_Wh)[i] = pack4(v.x, v.y, v.z, v.w);
}

// ---- prologue 2: gather + feature build -> fp16 feats ----
// One warp per output row (8 rows / 256-thr CTA, grid 2048).
__global__ void __launch_bounds__(256)
feats_kernel(const int* __restrict__ pairs32, const float* __restrict__ hidden) {
    __shared__ int sIs64;
    const int t    = threadIdx.x;
    const int lane = t & 31;
    const int wid  = t >> 5;

    if (t == 0) {   // int64 pairs -> all odd 32-bit words zero (indices < 1024)
        int a = 0;
#pragma unroll
        for (int i = 1; i < 128; i += 2) a |= pairs32[i];
        sIs64 = (a == 0);
    }
    __syncthreads();

    const int row = blockIdx.x * 8 + wid;     // 0..16383
    const int b   = row >> 9;
    const size_t pidx = (size_t)row;          // == b*512 + p
    int4 id;
    if (sIs64) {
        const long long* p64 = reinterpret_cast<const long long*>(pairs32) + pidx * 4;
        id = make_int4((int)p64[0], (int)p64[1], (int)p64[2], (int)p64[3]);
    } else {
        id = reinterpret_cast<const int4*>(pairs32)[pidx];
    }

    const float* hb = hidden + (size_t)b * (size_t)(1024 * 1024);
    const float4* x0 = reinterpret_cast<const float4*>(hb + (size_t)id.x * 1024);
    const float4* x1 = reinterpret_cast<const float4*>(hb + (size_t)id.y * 1024);
    const float4* x2 = reinterpret_cast<const float4*>(hb + (size_t)id.z * 1024);
    const float4* x3 = reinterpret_cast<const float4*>(hb + (size_t)id.w * 1024);
    uint2* fr = reinterpret_cast<uint2*>(g_feats + (size_t)row * 3072);

#pragma unroll
    for (int j = 0; j < 8; ++j) {
        const int i = lane + j * 32;          // float4 index 0..255
        float4 a = x0[i], d = x1[i], e = x2[i], f = x3[i];
        float hx = 0.5f*(a.x+d.x), hy = 0.5f*(a.y+d.y),
              hz = 0.5f*(a.z+d.z), hw = 0.5f*(a.w+d.w);
        float tx = 0.5f*(e.x+f.x), ty = 0.5f*(e.y+f.y),
              tz = 0.5f*(e.z+f.z), tw = 0.5f*(e.w+f.w);
        fr[i]       = pack4(hx, hy, hz, hw);
        fr[i + 256] = pack4(tx, ty, tz, tw);
        fr[i + 512] = pack4(hx*tx, hy*ty, hz*tz, hw*tw);
    }
}

// ---- main GEMM: A and B both via cp.async, 2-stage pipeline ----
__global__ void __launch_bounds__(THREADS, 1)
gr_gemm_kernel(const float* __restrict__ bias, float* __restrict__ out)
{
    constexpr int KC  = 64;
    constexpr int NCH = 3072 / KC;   // 48

    extern __shared__ char dsm[];
    const uint32_t smb = smem_u32(dsm);
    __shared__ float sBias[256];

    const int t    = threadIdx.x;
    const int lane = t & 31;
    const int w    = t >> 5;
    const int wm   = w >> 2;       // 0..1
    const int wn   = w & 3;        // 0..3
    const int row0 = blockIdx.x * 128;

    sBias[t] = bias[t];

    // prefetch source pointers
    const int arow = t >> 1;
    const int ak   = (t & 1) << 5;             // fp16 col offset 0/32
    const __half* asrc = g_feats + (size_t)(row0 + arow) * 3072 + ak;
    const __half* bsrc = g_Wh + (size_t)t * 3072;
    const uint32_t adst = OFF_A + arow * PITCH + ak * 2;
    const uint32_t bdst = OFF_B + t * PITCH;

    auto prefetch = [&](int c) {
        const uint32_t buf = smb + (c & 1) * BUF_STRIDE;
        const __half* as = asrc + c * KC;
        const __half* bs = bsrc + c * KC;
#pragma unroll
        for (int i = 0; i < 4; ++i)
            cpasync16(buf + adst + i * 16, as + i * 8);
#pragma unroll
        for (int i = 0; i < 8; ++i)
            cpasync16(buf + bdst + i * 16, bs + i * 8);
        asm volatile("cp.async.commit_group;");
    };

    float acc[4][8][4];
#pragma unroll
    for (int i = 0; i < 4; ++i)
#pragma unroll
        for (int j = 0; j < 8; ++j)
#pragma unroll
            for (int q = 0; q < 4; ++q) acc[i][j][q] = 0.f;

    const int lr = lane & 15;
    const int lh = (lane >> 4) << 3;
    const uint32_t aOff = OFF_A + (wm * 64 + lr) * PITCH + lh * 2;
    const uint32_t bOff = OFF_B + (wn * 64 + lr) * PITCH + lh * 2;

    prefetch(0);
    prefetch(1);

    for (int c = 0; c < NCH; ++c) {
        if (c >= NCH - 2) { asm volatile("cp.async.wait_group 0;" ::: "memory"); }
        else              { asm volatile("cp.async.wait_group 1;" ::: "memory"); }
        __syncthreads();

        const uint32_t base  = smb + (c & 1) * BUF_STRIDE;
        const uint32_t aBase = base + aOff;
        const uint32_t bBase = base + bOff;
#pragma unroll
        for (int kk = 0; kk < 4; ++kk) {
            const uint32_t kb = kk * 32;
            uint32_t af[4][4], bf[8][2];
#pragma unroll
            for (int mt = 0; mt < 4; ++mt)
                ldsm4(af[mt], aBase + mt * 16 * PITCH + kb);
#pragma unroll
            for (int p = 0; p < 4; ++p) {
                uint32_t r[4];
                ldsm4(r, bBase + p * 16 * PITCH + kb);
                bf[2*p][0]   = r[0]; bf[2*p][1]   = r[2];
                bf[2*p+1][0] = r[1]; bf[2*p+1][1] = r[3];
            }
#pragma unroll
            for (int mt = 0; mt < 4; ++mt)
#pragma unroll
                for (int n8 = 0; n8 < 8; ++n8)
                    mma_f16(acc[mt][n8], af[mt], bf[n8]);
        }

        __syncthreads();                       // all warps done reading buffer c&1
        if (c + 2 < NCH) prefetch(c + 2);      // refill the buffer just freed
    }

    // ---- epilogue: bias + fp32 store ----
    const int g  = lane >> 2;
    const int tq = lane & 3;
#pragma unroll
    for (int mt = 0; mt < 4; ++mt) {
        const int r0g = row0 + wm * 64 + mt * 16 + g;
#pragma unroll
        for (int n8 = 0; n8 < 8; ++n8) {
            const int col = wn * 64 + n8 * 8 + tq * 2;
            const float bx = sBias[col], by = sBias[col + 1];
            float* o0 = out + (size_t)r0g * 256 + col;
            float* o1 = o0 + 8 * 256;
            *reinterpret_cast<float2*>(o0) =
                make_float2(acc[mt][n8][0] + bx, acc[mt][n8][1] + by);
            *reinterpret_cast<float2*>(o1) =
                make_float2(acc[mt][n8][2] + bx, acc[mt][n8][3] + by);
        }
    }
}

extern "C" void kernel_launch(void* const* d_in, const int* in_sizes, int n_in,
                              void* d_out, int out_size) {
    (void)in_sizes; (void)n_in; (void)out_size;
    const int*   pairs  = (const int*)  d_in[0];
    const float* hidden = (const float*)d_in[1];
    const float* W      = (const float*)d_in[2];
    const float* bias   = (const float*)d_in[3];
    float*       out    = (float*)d_out;

    static bool attr_set = false;
    if (!attr_set) {
        cudaFuncSetAttribute(gr_gemm_kernel,
                             cudaFuncAttributeMaxDynamicSharedMemorySize, SMEM_BYTES);
        attr_set = true;
    }
    w_cvt_kernel<<<(256 * 3072 / 4 + 255) / 256, 256>>>(W);
    feats_kernel<<<16384 / 8, 256>>>(pairs, hidden);
    gr_gemm_kernel<<<16384 / 128, THREADS, SMEM_BYTES>>>(bias, out);
}